// round 10
// baseline (speedup 1.0000x reference)
#include <cuda_runtime.h>
#include <cuda_fp16.h>

// VectorQuantizer: z [32,4096,64] fp32, W [512,64] fp32.
// Out fp32: z_q_st (8388608) | indices-as-float (131072) | loss (1).
//
// R10: R7 base (512 thr, no spills) + filter loop unrolled 2x with
// independent HMMA accumulator chains (ILP to hide LDS/tensor latency at
// the reg-limited 4 warps/SMSP) + per-thread running-min threshold (no
// shfl/ballot). Deferred exact rescore with the bitwise reference chain;
// fused fixed-point deterministic loss (proven R7/R9).

#define DIM       64
#define KCODES    512
#define NROWS     131072
#define ROWS_CTA  256
#define GRIDM     (NROWS / ROWS_CTA)     // 512
#define THREADS   512
#define NELEM_ZQ  (NROWS * DIM)
#define SZ_STRIDE 66                     // fp32 row stride in smem (words)
#define SW_STRIDE 36                     // fp16-pair row stride (words)
#define CAP       12288                  // candidate entries

typedef unsigned int u32;
typedef unsigned long long u64;

__device__ u64 g_acc  = 0ull;            // fixed-point loss accumulator
__device__ u32 g_done = 0u;              // CTA completion counter

__device__ __forceinline__ u32 fflip(float x) {
    u32 u = __float_as_uint(x);
    return (u & 0x80000000u) ? ~u : (u | 0x80000000u);
}

// smem offsets (bytes)
#define OFF_SBEST 0
#define OFF_SRED  2048
#define OFF_SZ    6144
#define OFF_SW    (OFF_SZ + ROWS_CTA * SZ_STRIDE * 4)
#define OFF_WSQ   (OFF_SW + KCODES * SW_STRIDE * 4)
#define OFF_ZZ    (OFF_WSQ + KCODES * 4)
#define OFF_WID   (OFF_ZZ + ROWS_CTA * 4)
#define OFF_CAND  (OFF_WID + ROWS_CTA * 4)
#define OFF_CTL   (OFF_CAND + CAP * 4)
#define SMEM_TOT  (OFF_CTL + 16)

#define HMMA4(cc, AA, bb0, bb1)                                              \
    asm volatile(                                                            \
        "mma.sync.aligned.m16n8k16.row.col.f32.f16.f16.f32 "                 \
        "{%0,%1,%2,%3}, {%4,%5,%6,%7}, {%8,%9}, {%0,%1,%2,%3};"              \
        : "+f"(cc[0]), "+f"(cc[1]), "+f"(cc[2]), "+f"(cc[3])                 \
        : "r"(AA[0]), "r"(AA[1]), "r"(AA[2]), "r"(AA[3]), "r"(bb0), "r"(bb1))

__global__ __launch_bounds__(THREADS, 1)
void vq_all(const float* __restrict__ z, const float* __restrict__ W,
            float* __restrict__ out, int out_size) {
    extern __shared__ char smraw[];
    u64*    sbest = (u64*)(smraw + OFF_SBEST);     // 256
    double* sred  = (double*)(smraw + OFF_SRED);   // 512
    float*  sz    = (float*)(smraw + OFF_SZ);      // 256 x 66
    u32*    sW    = (u32*)(smraw + OFF_SW);        // 512 x 36 (fp16x2)
    float*  swsq  = (float*)(smraw + OFF_WSQ);     // 512
    float*  szz   = (float*)(smraw + OFF_ZZ);      // 256
    float*  swid  = (float*)(smraw + OFF_WID);     // 256
    u32*    scand = (u32*)(smraw + OFF_CAND);      // CAP
    u32*    sctl  = (u32*)(smraw + OFF_CTL);       // cnt, ovf

    const int tid  = threadIdx.x;
    const int lane = tid & 31;
    const int wid  = tid >> 5;                     // 0..15
    const int gid  = lane >> 2;
    const int tig  = lane & 3;
    const int rowbase = blockIdx.x * ROWS_CTA;
    const u32 FULL = 0xFFFFFFFFu;

    // ===== Phase 1: wsq via two coalesced 256-row chunks through sz =====
    #pragma unroll 1
    for (int c = 0; c < 2; c++) {
        const float2* Wg = (const float2*)(W + (size_t)c * 256 * DIM);
        for (int i = tid; i < 256 * (DIM / 2); i += THREADS) {
            int r = i >> 5, kw = i & 31;
            *(float2*)(sz + r * SZ_STRIDE + kw * 2) = Wg[i];
        }
        __syncthreads();
        if (tid < 256) {
            const float* w = sz + tid * SZ_STRIDE;
            float acc = 0.0f;
            #pragma unroll
            for (int k = 0; k < DIM; k++)
                acc = __fadd_rn(acc, __fmul_rn(w[k], w[k]));
            swsq[c * 256 + tid] = acc;   // exact sequential reference chain
        }
        __syncthreads();
    }

    // ===== Phase 2: wmax = max ||w_j|| (tree in sred scratch) =====
    float wmax;
    {
        float* fs = (float*)sred;
        fs[tid] = fmaxf(sqrtf(swsq[tid]), sqrtf(swsq[tid + 256]));
        __syncthreads();
        #pragma unroll
        for (int s = 256; s > 0; s >>= 1) {
            if (tid < s) fs[tid] = fmaxf(fs[tid], fs[tid + s]);
            __syncthreads();
        }
        wmax = fs[0] * 1.0001f;
        __syncthreads();
    }

    // ===== Phase 3: stage z (overwrites sz), fp16 W, init =====
    {
        const float2* zg = (const float2*)(z + (size_t)rowbase * DIM);
        for (int i = tid; i < ROWS_CTA * (DIM / 2); i += THREADS) {
            int r = i >> 5, c2 = i & 31;
            *(float2*)(sz + r * SZ_STRIDE + c2 * 2) = zg[i];
        }
        for (int i = tid; i < KCODES * (DIM / 2); i += THREADS) {
            int j = i >> 5, kw = i & 31;
            float2 g = ((const float2*)W)[i];
            __half2 h = __float22half2_rn(g);
            sW[j * SW_STRIDE + kw] = *(u32*)&h;
        }
        if (tid < ROWS_CTA) sbest[tid] = ~0ull;
        if (tid == 0) { sctl[0] = 0; sctl[1] = 0; }
        __syncthreads();
    }

    // ===== Phase 4: exact zz per row + rigorous width =====
    if (tid < ROWS_CTA) {
        const float* zr = sz + tid * SZ_STRIDE;
        float acc = 0.0f;
        #pragma unroll
        for (int k = 0; k < DIM; k++)
            acc = __fadd_rn(acc, __fmul_rn(zr[k], zr[k]));
        szz[tid] = acc;
        float znorm = sqrtf(acc) * 1.0001f;
        swid[tid] = 4.1e-3f * znorm * wmax + 1.1e-6f * znorm + 4.0e-5f;
    }
    __syncthreads();

    // ===== Phase 5: A fragments (rows m0, m0+8) fp16 from smem =====
    const int m0 = wid * 16 + gid;
    u32 A[4][4];
    #pragma unroll
    for (int kk = 0; kk < 4; kk++) {
        int kb = kk * 16;
        float2 p0 = *(float2*)(sz + m0 * SZ_STRIDE + kb + tig * 2);
        float2 p1 = *(float2*)(sz + (m0 + 8) * SZ_STRIDE + kb + tig * 2);
        float2 p2 = *(float2*)(sz + m0 * SZ_STRIDE + kb + 8 + tig * 2);
        float2 p3 = *(float2*)(sz + (m0 + 8) * SZ_STRIDE + kb + 8 + tig * 2);
        __half2 h;
        h = __float22half2_rn(p0); A[kk][0] = *(u32*)&h;
        h = __float22half2_rn(p1); A[kk][1] = *(u32*)&h;
        h = __float22half2_rn(p2); A[kk][2] = *(u32*)&h;
        h = __float22half2_rn(p3); A[kk][3] = *(u32*)&h;
    }

    // ===== Phase 6: filter, unroll 2 blocks/iter, per-thread running min ====
    // superset proof (order-independent): rmin >= global min always, and
    // s_{j*} <= global_min + width  =>  s_{j*} <= rmin + width  => recorded.
    {
        const float widA = swid[m0], widB = swid[m0 + 8];
        float rminA = 3.0e38f, rminB = 3.0e38f;

        #pragma unroll 1
        for (int it = 0; it < 32; it++) {
            const int j0 = it * 16;                 // blocks j0 and j0+8
            float c[4] = {0.f, 0.f, 0.f, 0.f};      // block X accumulators
            float e[4] = {0.f, 0.f, 0.f, 0.f};      // block Y accumulators
            const u32* wrowX = sW + (j0 + gid) * SW_STRIDE + tig;
            const u32* wrowY = wrowX + 8 * SW_STRIDE;

            #pragma unroll
            for (int kk = 0; kk < 4; kk++) {
                u32 bx0 = wrowX[kk * 8];
                u32 bx1 = wrowX[kk * 8 + 4];
                u32 by0 = wrowY[kk * 8];
                u32 by1 = wrowY[kk * 8 + 4];
                HMMA4(c, A[kk], bx0, bx1);
                HMMA4(e, A[kk], by0, by1);
            }

            const int jx = j0 + tig * 2;            // block X codes
            const int jy = jx + 8;                  // block Y codes
            float wx0 = swsq[jx], wx1 = swsq[jx + 1];
            float wy0 = swsq[jy], wy1 = swsq[jy + 1];
            float sx0 = __fsub_rn(wx0, __fmul_rn(2.0f, c[0]));
            float sx1 = __fsub_rn(wx1, __fmul_rn(2.0f, c[1]));
            float sx2 = __fsub_rn(wx0, __fmul_rn(2.0f, c[2]));
            float sx3 = __fsub_rn(wx1, __fmul_rn(2.0f, c[3]));
            float sy0 = __fsub_rn(wy0, __fmul_rn(2.0f, e[0]));
            float sy1 = __fsub_rn(wy1, __fmul_rn(2.0f, e[1]));
            float sy2 = __fsub_rn(wy0, __fmul_rn(2.0f, e[2]));
            float sy3 = __fsub_rn(wy1, __fmul_rn(2.0f, e[3]));

            rminA = fminf(rminA, fminf(fminf(sx0, sx1), fminf(sy0, sy1)));
            rminB = fminf(rminB, fminf(fminf(sx2, sx3), fminf(sy2, sy3)));
            const float tA = rminA + widA, tB = rminB + widB;

            if (sx0 <= tA) { u32 x = atomicAdd(&sctl[0], 1u);
                if (x < CAP) scand[x] = ((u32)m0 << 9) | (u32)jx; else atomicExch(&sctl[1], 1u); }
            if (sx1 <= tA) { u32 x = atomicAdd(&sctl[0], 1u);
                if (x < CAP) scand[x] = ((u32)m0 << 9) | (u32)(jx + 1); else atomicExch(&sctl[1], 1u); }
            if (sy0 <= tA) { u32 x = atomicAdd(&sctl[0], 1u);
                if (x < CAP) scand[x] = ((u32)m0 << 9) | (u32)jy; else atomicExch(&sctl[1], 1u); }
            if (sy1 <= tA) { u32 x = atomicAdd(&sctl[0], 1u);
                if (x < CAP) scand[x] = ((u32)m0 << 9) | (u32)(jy + 1); else atomicExch(&sctl[1], 1u); }
            if (sx2 <= tB) { u32 x = atomicAdd(&sctl[0], 1u);
                if (x < CAP) scand[x] = ((u32)(m0 + 8) << 9) | (u32)jx; else atomicExch(&sctl[1], 1u); }
            if (sx3 <= tB) { u32 x = atomicAdd(&sctl[0], 1u);
                if (x < CAP) scand[x] = ((u32)(m0 + 8) << 9) | (u32)(jx + 1); else atomicExch(&sctl[1], 1u); }
            if (sy2 <= tB) { u32 x = atomicAdd(&sctl[0], 1u);
                if (x < CAP) scand[x] = ((u32)(m0 + 8) << 9) | (u32)jy; else atomicExch(&sctl[1], 1u); }
            if (sy3 <= tB) { u32 x = atomicAdd(&sctl[0], 1u);
                if (x < CAP) scand[x] = ((u32)(m0 + 8) << 9) | (u32)(jy + 1); else atomicExch(&sctl[1], 1u); }
        }
    }
    __syncthreads();

    // ===== Phase 7: deferred exact rescore (bitwise reference chain) =====
    if (sctl[1] == 0) {
        int n = min(sctl[0], (u32)CAP);
        for (int c = tid; c < n; c += THREADS) {
            u32 e = scand[c];
            int r = e >> 9, j = e & 511;
            const float* zr = sz + r * SZ_STRIDE;
            const float* wr = W + j * DIM;
            float acc = 0.0f;
            #pragma unroll
            for (int k = 0; k < DIM; k += 4) {
                float2 za = *(const float2*)(zr + k);
                float2 zb = *(const float2*)(zr + k + 2);
                float4 wv = *(const float4*)(wr + k);
                acc = __fmaf_rn(za.x, wv.x, acc);
                acc = __fmaf_rn(za.y, wv.y, acc);
                acc = __fmaf_rn(zb.x, wv.z, acc);
                acc = __fmaf_rn(zb.y, wv.w, acc);
            }
            float dist = __fsub_rn(__fadd_rn(szz[r], swsq[j]), __fmul_rn(2.0f, acc));
            atomicMin(&sbest[r], ((u64)fflip(dist) << 32) | (u32)j);
        }
    } else {
        // overflow fallback: warp-cooperative full exact scan (always correct)
        for (int r = wid; r < ROWS_CTA; r += THREADS / 32) {
            const float* zr = sz + r * SZ_STRIDE;
            u64 best = ~0ull;
            for (int j = lane; j < KCODES; j += 32) {
                const float* wr = W + j * DIM;
                float acc = 0.0f;
                #pragma unroll
                for (int k = 0; k < DIM; k += 4) {
                    float2 za = *(const float2*)(zr + k);
                    float2 zb = *(const float2*)(zr + k + 2);
                    float4 wv = *(const float4*)(wr + k);
                    acc = __fmaf_rn(za.x, wv.x, acc);
                    acc = __fmaf_rn(za.y, wv.y, acc);
                    acc = __fmaf_rn(zb.x, wv.z, acc);
                    acc = __fmaf_rn(zb.y, wv.w, acc);
                }
                float dist = __fsub_rn(__fadd_rn(szz[r], swsq[j]), __fmul_rn(2.0f, acc));
                best = min(best, ((u64)fflip(dist) << 32) | (u32)j);
            }
            #pragma unroll
            for (int off = 16; off > 0; off >>= 1)
                best = min(best, __shfl_xor_sync(FULL, best, off));
            if (lane == 0) atomicMin(&sbest[r], best);
        }
    }
    __syncthreads();

    // ===== Phase 8: epilogue (coalesced) + deterministic loss =====
    double dsum = 0.0;
    for (int i = tid; i < ROWS_CTA * DIM; i += THREADS) {
        int r = i >> 6, k = i & 63;
        int bj = (int)(sbest[r] & 0xFFFFFFFFull);
        float zv = sz[r * SZ_STRIDE + k];
        float wv = __ldg(W + bj * DIM + k);
        float st = __fadd_rn(zv, __fsub_rn(wv, zv));
        float df = __fsub_rn(zv, st);
        dsum += (double)__fmul_rn(df, df);
        out[(size_t)rowbase * DIM + i] = st;
    }
    if (tid < ROWS_CTA && out_size > NELEM_ZQ + rowbase + tid)
        out[NELEM_ZQ + rowbase + tid] = (float)(sbest[tid] & 0xFFFFFFFFull);

    sred[tid] = dsum;
    __syncthreads();
    #pragma unroll
    for (int s = THREADS / 2; s > 0; s >>= 1) {
        if (tid < s) sred[tid] += sred[tid + s];
        __syncthreads();
    }
    if (tid == 0) {
        // fixed-point (2^20) order-independent accumulation -> deterministic
        u64 part = (u64)__double2ll_rn(sred[0] * 1048576.0);
        atomicAdd(&g_acc, part);
        __threadfence();
        u32 t = atomicAdd(&g_done, 1u);
        if (t == GRIDM - 1) {                 // last CTA finalizes + resets
            u64 tot = atomicExch(&g_acc, 0ull);
            atomicExch(&g_done, 0u);
            double s = (double)tot * (1.0 / 1048576.0);
            int lp = NELEM_ZQ + NROWS;
            if (out_size > lp)
                out[lp] = (float)(0.25 * s / (double)NELEM_ZQ);
        }
    }
}

extern "C" void kernel_launch(void* const* d_in, const int* in_sizes, int n_in,
                              void* d_out, int out_size) {
    const float* z = (const float*)d_in[0];
    const float* W = (const float*)d_in[1];
    float* out = (float*)d_out;

    static bool attr_set = false;
    if (!attr_set) {
        cudaFuncSetAttribute(vq_all, cudaFuncAttributeMaxDynamicSharedMemorySize,
                             SMEM_TOT);
        attr_set = true;
    }

    vq_all<<<GRIDM, THREADS, SMEM_TOT>>>(z, W, out, out_size);
}

// round 11
// speedup vs baseline: 33.7519x; 33.7519x over previous
#include <cuda_runtime.h>
#include <cuda_fp16.h>

// VectorQuantizer: z [32,4096,64] fp32, W [512,64] fp32.
// Out fp32: z_q_st (8388608) | indices-as-float (131072) | loss (1).
//
// R11: two-pass exact-threshold fp16 mma filter (pass1 true min, pass2
// record; candidates ~6/row -> overflow unreachable), 256thr/128rows with
// __launch_bounds__(256,2) for 2 CTAs/SM (32k regs each), XOR-swizzled W
// smem (stride 32, conflict-free). Exact rescore = bitwise reference chain;
// fused fixed-point deterministic loss (proven R7).

#define DIM       64
#define KCODES    512
#define NROWS     131072
#define ROWS_CTA  128
#define GRIDM     (NROWS / ROWS_CTA)     // 1024
#define THREADS   256
#define NELEM_ZQ  (NROWS * DIM)
#define SZ_STRIDE 66                     // fp32 z row stride (words)
#define CAP       1536                   // candidate entries

typedef unsigned int u32;
typedef unsigned long long u64;

__device__ u64 g_acc  = 0ull;            // fixed-point loss accumulator
__device__ u32 g_done = 0u;              // CTA completion counter
__device__ u32 g_Wh[KCODES * (DIM / 2)]; // fp16x2 codebook
__device__ float g_wsq[KCODES];
__device__ u32 g_wmax_bits = 0u;         // fflip-encoded max ||w||

__device__ __forceinline__ u32 fflip(float x) {
    u32 u = __float_as_uint(x);
    return (u & 0x80000000u) ? ~u : (u | 0x80000000u);
}
__device__ __forceinline__ float funflip(u32 u) {
    return (u & 0x80000000u) ? __uint_as_float(u ^ 0x80000000u)
                             : __uint_as_float(~u);
}

// smem offsets (bytes)
#define OFF_SBEST 0                                    // 128*8
#define OFF_SRED  1024                                 // 256*8
#define OFF_SZ    3072                                 // 128*66*4 = 33792
#define OFF_SW    (OFF_SZ + ROWS_CTA * SZ_STRIDE * 4)  // 36864; 512*32*4
#define OFF_WSQ   (OFF_SW + KCODES * 32 * 4)           // 102400; 512*4
#define OFF_ZZ    (OFF_WSQ + KCODES * 4)               // 104448; 128*4
#define OFF_WID   (OFF_ZZ + ROWS_CTA * 4)              // 104960; 128*4
#define OFF_CAND  (OFF_WID + ROWS_CTA * 4)             // 105472; CAP*4
#define OFF_CTL   (OFF_CAND + CAP * 4)                 // 111616
#define SMEM_TOT  (OFF_CTL + 16)                       // 111632 (x2 fits SM)

// XOR swizzle: word w (0..31) of code j lives at j*32 + (w ^ ((j&7)<<2))
#define SWIZ(j, w) (((j) << 5) | ((w) ^ (((j) & 7) << 2)))

#define HMMA4(cc, AA, bb0, bb1)                                              \
    asm volatile(                                                            \
        "mma.sync.aligned.m16n8k16.row.col.f32.f16.f16.f32 "                 \
        "{%0,%1,%2,%3}, {%4,%5,%6,%7}, {%8,%9}, {%0,%1,%2,%3};"              \
        : "+f"(cc[0]), "+f"(cc[1]), "+f"(cc[2]), "+f"(cc[3])                 \
        : "r"(AA[0]), "r"(AA[1]), "r"(AA[2]), "r"(AA[3]), "r"(bb0), "r"(bb1))

// ---------------------------------------------------------------------------
// Prep: 4 blocks x 128 thr. wsq via coalesced smem stage + exact chain;
// fp16 convert coalesced; wmax via block-reduce + atomicMax (idempotent).
// ---------------------------------------------------------------------------
__global__ void prep_kernel(const float* __restrict__ W) {
    __shared__ float sw[128 * 65];
    __shared__ float red[128];
    const int tid = threadIdx.x;
    const int jb  = blockIdx.x * 128;

    for (int i = tid; i < 128 * DIM; i += 128) {
        int j = i >> 6, k = i & 63;
        sw[j * 65 + k] = W[(size_t)jb * DIM + i];
    }
    __syncthreads();

    const float* wr = sw + tid * 65;
    float acc = 0.0f;
    #pragma unroll
    for (int k = 0; k < DIM; k++)
        acc = __fadd_rn(acc, __fmul_rn(wr[k], wr[k]));   // exact ref chain
    g_wsq[jb + tid] = acc;

    for (int i = tid; i < 128 * (DIM / 2); i += 128) {
        float2 g = ((const float2*)W)[jb * (DIM / 2) + i];
        __half2 h = __float22half2_rn(g);
        g_Wh[jb * (DIM / 2) + i] = *(u32*)&h;
    }

    red[tid] = sqrtf(acc);
    __syncthreads();
    #pragma unroll
    for (int s = 64; s > 0; s >>= 1) {
        if (tid < s) red[tid] = fmaxf(red[tid], red[tid + s]);
        __syncthreads();
    }
    if (tid == 0) atomicMax(&g_wmax_bits, fflip(red[0]));
}

// ---------------------------------------------------------------------------
__global__ __launch_bounds__(THREADS, 2)
void vq_main(const float* __restrict__ z, const float* __restrict__ W,
             float* __restrict__ out, int out_size) {
    extern __shared__ char smraw[];
    u64*    sbest = (u64*)(smraw + OFF_SBEST);
    double* sred  = (double*)(smraw + OFF_SRED);
    float*  sz    = (float*)(smraw + OFF_SZ);
    u32*    sW    = (u32*)(smraw + OFF_SW);
    float*  swsq  = (float*)(smraw + OFF_WSQ);
    float*  szz   = (float*)(smraw + OFF_ZZ);
    float*  swid  = (float*)(smraw + OFF_WID);
    u32*    scand = (u32*)(smraw + OFF_CAND);
    u32*    sctl  = (u32*)(smraw + OFF_CTL);

    const int tid  = threadIdx.x;
    const int lane = tid & 31;
    const int wid  = tid >> 5;                     // 0..7
    const int gid  = lane >> 2;
    const int tig  = lane & 3;
    const int rowbase = blockIdx.x * ROWS_CTA;
    const u32 FULL = 0xFFFFFFFFu;
    const float wmax = funflip(g_wmax_bits) * 1.0001f;

    // ---- stage z, swizzled fp16 W, wsq; init ----
    {
        const float2* zg = (const float2*)(z + (size_t)rowbase * DIM);
        for (int i = tid; i < ROWS_CTA * (DIM / 2); i += THREADS) {
            int r = i >> 5, c2 = i & 31;
            *(float2*)(sz + r * SZ_STRIDE + c2 * 2) = zg[i];
        }
        for (int i = tid; i < KCODES * (DIM / 2); i += THREADS) {
            int j = i >> 5, w = i & 31;
            sW[SWIZ(j, w)] = g_Wh[i];
        }
        for (int i = tid; i < KCODES; i += THREADS) swsq[i] = g_wsq[i];
        if (tid < ROWS_CTA) sbest[tid] = ~0ull;
        if (tid == 0) { sctl[0] = 0; sctl[1] = 0; }
        __syncthreads();
    }

    // ---- exact zz per row + rigorous width (128 threads) ----
    if (tid < ROWS_CTA) {
        const float* zr = sz + tid * SZ_STRIDE;
        float acc = 0.0f;
        #pragma unroll
        for (int k = 0; k < DIM; k++)
            acc = __fadd_rn(acc, __fmul_rn(zr[k], zr[k]));
        szz[tid] = acc;
        float znorm = sqrtf(acc) * 1.0001f;
        swid[tid] = 4.1e-3f * znorm * wmax + 1.1e-6f * znorm + 4.0e-5f;
    }
    __syncthreads();

    // ---- A fragments (rows m0, m0+8) fp16 from smem ----
    const int m0 = wid * 16 + gid;
    u32 A[4][4];
    #pragma unroll
    for (int kk = 0; kk < 4; kk++) {
        int kb = kk * 16;
        float2 p0 = *(float2*)(sz + m0 * SZ_STRIDE + kb + tig * 2);
        float2 p1 = *(float2*)(sz + (m0 + 8) * SZ_STRIDE + kb + tig * 2);
        float2 p2 = *(float2*)(sz + m0 * SZ_STRIDE + kb + 8 + tig * 2);
        float2 p3 = *(float2*)(sz + (m0 + 8) * SZ_STRIDE + kb + 8 + tig * 2);
        __half2 h;
        h = __float22half2_rn(p0); A[kk][0] = *(u32*)&h;
        h = __float22half2_rn(p1); A[kk][1] = *(u32*)&h;
        h = __float22half2_rn(p2); A[kk][2] = *(u32*)&h;
        h = __float22half2_rn(p3); A[kk][3] = *(u32*)&h;
    }

    // ===== PASS 1: true filter min (2-block unroll, independent chains) ====
    float rminA = 3.0e38f, rminB = 3.0e38f;
    #pragma unroll 1
    for (int it = 0; it < 32; it++) {
        const int j0 = it * 16;
        float c[4] = {0.f, 0.f, 0.f, 0.f};
        float e[4] = {0.f, 0.f, 0.f, 0.f};
        #pragma unroll
        for (int kk = 0; kk < 4; kk++) {
            u32 bx0 = sW[SWIZ(j0 + gid,     kk * 8 + tig)];
            u32 bx1 = sW[SWIZ(j0 + gid,     kk * 8 + 4 + tig)];
            u32 by0 = sW[SWIZ(j0 + 8 + gid, kk * 8 + tig)];
            u32 by1 = sW[SWIZ(j0 + 8 + gid, kk * 8 + 4 + tig)];
            HMMA4(c, A[kk], bx0, bx1);
            HMMA4(e, A[kk], by0, by1);
        }
        const int jx = j0 + tig * 2, jy = jx + 8;
        float wx0 = swsq[jx], wx1 = swsq[jx + 1];
        float wy0 = swsq[jy], wy1 = swsq[jy + 1];
        rminA = fminf(rminA, fminf(
            fminf(__fsub_rn(wx0, __fmul_rn(2.0f, c[0])),
                  __fsub_rn(wx1, __fmul_rn(2.0f, c[1]))),
            fminf(__fsub_rn(wy0, __fmul_rn(2.0f, e[0])),
                  __fsub_rn(wy1, __fmul_rn(2.0f, e[1])))));
        rminB = fminf(rminB, fminf(
            fminf(__fsub_rn(wx0, __fmul_rn(2.0f, c[2])),
                  __fsub_rn(wx1, __fmul_rn(2.0f, c[3]))),
            fminf(__fsub_rn(wy0, __fmul_rn(2.0f, e[2])),
                  __fsub_rn(wy1, __fmul_rn(2.0f, e[3])))));
    }
    // combine tig lanes once -> TRUE per-row filter min; thresholds in regs
    rminA = fminf(rminA, __shfl_xor_sync(FULL, rminA, 1));
    rminA = fminf(rminA, __shfl_xor_sync(FULL, rminA, 2));
    rminB = fminf(rminB, __shfl_xor_sync(FULL, rminB, 1));
    rminB = fminf(rminB, __shfl_xor_sync(FULL, rminB, 2));
    const float tA = rminA + swid[m0];
    const float tB = rminB + swid[m0 + 8];

    // ===== PASS 2: record candidates vs exact threshold =====
    #pragma unroll 1
    for (int it = 0; it < 32; it++) {
        const int j0 = it * 16;
        float c[4] = {0.f, 0.f, 0.f, 0.f};
        float e[4] = {0.f, 0.f, 0.f, 0.f};
        #pragma unroll
        for (int kk = 0; kk < 4; kk++) {
            u32 bx0 = sW[SWIZ(j0 + gid,     kk * 8 + tig)];
            u32 bx1 = sW[SWIZ(j0 + gid,     kk * 8 + 4 + tig)];
            u32 by0 = sW[SWIZ(j0 + 8 + gid, kk * 8 + tig)];
            u32 by1 = sW[SWIZ(j0 + 8 + gid, kk * 8 + 4 + tig)];
            HMMA4(c, A[kk], bx0, bx1);
            HMMA4(e, A[kk], by0, by1);
        }
        const int jx = j0 + tig * 2, jy = jx + 8;
        float wx0 = swsq[jx], wx1 = swsq[jx + 1];
        float wy0 = swsq[jy], wy1 = swsq[jy + 1];
        float sx0 = __fsub_rn(wx0, __fmul_rn(2.0f, c[0]));
        float sx1 = __fsub_rn(wx1, __fmul_rn(2.0f, c[1]));
        float sx2 = __fsub_rn(wx0, __fmul_rn(2.0f, c[2]));
        float sx3 = __fsub_rn(wx1, __fmul_rn(2.0f, c[3]));
        float sy0 = __fsub_rn(wy0, __fmul_rn(2.0f, e[0]));
        float sy1 = __fsub_rn(wy1, __fmul_rn(2.0f, e[1]));
        float sy2 = __fsub_rn(wy0, __fmul_rn(2.0f, e[2]));
        float sy3 = __fsub_rn(wy1, __fmul_rn(2.0f, e[3]));

        if (sx0 <= tA) { u32 x = atomicAdd(&sctl[0], 1u);
            if (x < CAP) scand[x] = ((u32)m0 << 9) | (u32)jx; else atomicExch(&sctl[1], 1u); }
        if (sx1 <= tA) { u32 x = atomicAdd(&sctl[0], 1u);
            if (x < CAP) scand[x] = ((u32)m0 << 9) | (u32)(jx + 1); else atomicExch(&sctl[1], 1u); }
        if (sy0 <= tA) { u32 x = atomicAdd(&sctl[0], 1u);
            if (x < CAP) scand[x] = ((u32)m0 << 9) | (u32)jy; else atomicExch(&sctl[1], 1u); }
        if (sy1 <= tA) { u32 x = atomicAdd(&sctl[0], 1u);
            if (x < CAP) scand[x] = ((u32)m0 << 9) | (u32)(jy + 1); else atomicExch(&sctl[1], 1u); }
        if (sx2 <= tB) { u32 x = atomicAdd(&sctl[0], 1u);
            if (x < CAP) scand[x] = ((u32)(m0 + 8) << 9) | (u32)jx; else atomicExch(&sctl[1], 1u); }
        if (sx3 <= tB) { u32 x = atomicAdd(&sctl[0], 1u);
            if (x < CAP) scand[x] = ((u32)(m0 + 8) << 9) | (u32)(jx + 1); else atomicExch(&sctl[1], 1u); }
        if (sy2 <= tB) { u32 x = atomicAdd(&sctl[0], 1u);
            if (x < CAP) scand[x] = ((u32)(m0 + 8) << 9) | (u32)jy; else atomicExch(&sctl[1], 1u); }
        if (sy3 <= tB) { u32 x = atomicAdd(&sctl[0], 1u);
            if (x < CAP) scand[x] = ((u32)(m0 + 8) << 9) | (u32)(jy + 1); else atomicExch(&sctl[1], 1u); }
    }
    __syncthreads();

    // ===== deferred exact rescore (bitwise reference chain) =====
    if (sctl[1] == 0) {
        int n = min(sctl[0], (u32)CAP);
        for (int c = tid; c < n; c += THREADS) {
            u32 e = scand[c];
            int r = e >> 9, j = e & 511;
            const float* zr = sz + r * SZ_STRIDE;
            const float* wr = W + j * DIM;
            float acc = 0.0f;
            #pragma unroll
            for (int k = 0; k < DIM; k += 4) {
                float2 za = *(const float2*)(zr + k);
                float2 zb = *(const float2*)(zr + k + 2);
                float4 wv = *(const float4*)(wr + k);
                acc = __fmaf_rn(za.x, wv.x, acc);
                acc = __fmaf_rn(za.y, wv.y, acc);
                acc = __fmaf_rn(zb.x, wv.z, acc);
                acc = __fmaf_rn(zb.y, wv.w, acc);
            }
            float dist = __fsub_rn(__fadd_rn(szz[r], swsq[j]), __fmul_rn(2.0f, acc));
            atomicMin(&sbest[r], ((u64)fflip(dist) << 32) | (u32)j);
        }
    } else {
        // overflow fallback (27-sigma unreachable): full exact scan
        for (int r = wid; r < ROWS_CTA; r += THREADS / 32) {
            const float* zr = sz + r * SZ_STRIDE;
            u64 best = ~0ull;
            for (int j = lane; j < KCODES; j += 32) {
                const float* wr = W + j * DIM;
                float acc = 0.0f;
                #pragma unroll
                for (int k = 0; k < DIM; k += 4) {
                    float2 za = *(const float2*)(zr + k);
                    float2 zb = *(const float2*)(zr + k + 2);
                    float4 wv = *(const float4*)(wr + k);
                    acc = __fmaf_rn(za.x, wv.x, acc);
                    acc = __fmaf_rn(za.y, wv.y, acc);
                    acc = __fmaf_rn(zb.x, wv.z, acc);
                    acc = __fmaf_rn(zb.y, wv.w, acc);
                }
                float dist = __fsub_rn(__fadd_rn(szz[r], swsq[j]), __fmul_rn(2.0f, acc));
                best = min(best, ((u64)fflip(dist) << 32) | (u32)j);
            }
            #pragma unroll
            for (int off = 16; off > 0; off >>= 1)
                best = min(best, __shfl_xor_sync(FULL, best, off));
            if (lane == 0) atomicMin(&sbest[r], best);
        }
    }
    __syncthreads();

    // ===== epilogue (coalesced) + deterministic fixed-point loss =====
    double dsum = 0.0;
    for (int i = tid; i < ROWS_CTA * DIM; i += THREADS) {
        int r = i >> 6, k = i & 63;
        int bj = (int)(sbest[r] & 0xFFFFFFFFull);
        float zv = sz[r * SZ_STRIDE + k];
        float wv = __ldg(W + bj * DIM + k);
        float st = __fadd_rn(zv, __fsub_rn(wv, zv));
        float df = __fsub_rn(zv, st);
        dsum += (double)__fmul_rn(df, df);
        out[(size_t)rowbase * DIM + i] = st;
    }
    if (tid < ROWS_CTA && out_size > NELEM_ZQ + rowbase + tid)
        out[NELEM_ZQ + rowbase + tid] = (float)(sbest[tid] & 0xFFFFFFFFull);

    sred[tid] = dsum;
    __syncthreads();
    #pragma unroll
    for (int s = THREADS / 2; s > 0; s >>= 1) {
        if (tid < s) sred[tid] += sred[tid + s];
        __syncthreads();
    }
    if (tid == 0) {
        u64 part = (u64)__double2ll_rn(sred[0] * 1048576.0);
        atomicAdd(&g_acc, part);
        __threadfence();
        u32 t = atomicAdd(&g_done, 1u);
        if (t == GRIDM - 1) {                 // last CTA finalizes + resets
            u64 tot = atomicExch(&g_acc, 0ull);
            atomicExch(&g_done, 0u);
            double s = (double)tot * (1.0 / 1048576.0);
            int lp = NELEM_ZQ + NROWS;
            if (out_size > lp)
                out[lp] = (float)(0.25 * s / (double)NELEM_ZQ);
        }
    }
}

extern "C" void kernel_launch(void* const* d_in, const int* in_sizes, int n_in,
                              void* d_out, int out_size) {
    const float* z = (const float*)d_in[0];
    const float* W = (const float*)d_in[1];
    float* out = (float*)d_out;

    static bool attr_set = false;
    if (!attr_set) {
        cudaFuncSetAttribute(vq_main, cudaFuncAttributeMaxDynamicSharedMemorySize,
                             SMEM_TOT);
        attr_set = true;
    }

    prep_kernel<<<4, 128>>>(W);
    vq_main<<<GRIDM, THREADS, SMEM_TOT>>>(z, W, out, out_size);
}